// round 6
// baseline (speedup 1.0000x reference)
#include <cuda_runtime.h>
#include <cstdint>

// SE block, one persistent kernel, 152 blocks (1/SM), grid barrier.
// Streaming via cp.async.bulk (TMA path) -> 4-deep smem pipeline:
//   Phase 1 (iters 0..26):  bulk-load 2 planes -> smem, reduce -> d_s
//   (grid barrier + tiny MLP; phase-3 loads already prefetching)
//   Phase 3 (iters 27..53): bulk-load 2 planes -> smem, scale -> STG.128 out
// Slot = iter & 3, parity = (iter >> 2) & 1 — one uniform ring across phases.

#define C           256
#define BOT         32
#define HW          3136
#define HW4         784
#define PLANE_BYTES (HW * 4)           // 12544
#define BC          8192
#define GRID        152
#define NTHREADS    1024
#define NBUF        4
#define PLB         2                  // planes per buffer
#define BUF_F       (PLB * HW)         // floats per buffer
#define ITERS       27                 // per phase (covers nk = 53/54)
#define TOTAL_ITERS (2 * ITERS)

struct __align__(128) Smem {
    float buf[NBUF][BUF_F];            // 100352 B
    unsigned long long mbar[NBUF];
    float pb[2][2][32];                // [iter&1][plane_in_buf][warp]
    float s[2][C];
    float h[2][BOT];
    float g[64];
};

__device__ float d_s[BC];
__device__ unsigned int d_arrive = 0;
__device__ volatile unsigned int d_gen = 0;

__device__ __forceinline__ unsigned smem_u32(const void* p) {
    return (unsigned)__cvta_generic_to_shared(p);
}
__device__ __forceinline__ void mbar_init(unsigned a, unsigned cnt) {
    asm volatile("mbarrier.init.shared.b64 [%0], %1;" :: "r"(a), "r"(cnt) : "memory");
}
__device__ __forceinline__ void mbar_expect_tx(unsigned a, unsigned bytes) {
    asm volatile("mbarrier.arrive.expect_tx.shared.b64 _, [%0], %1;"
                 :: "r"(a), "r"(bytes) : "memory");
}
__device__ __forceinline__ void bulk_ld(unsigned dst, const void* src,
                                        unsigned bytes, unsigned bar) {
    asm volatile(
        "cp.async.bulk.shared::cluster.global.mbarrier::complete_tx::bytes "
        "[%0], [%1], %2, [%3];"
        :: "r"(dst), "l"(src), "r"(bytes), "r"(bar) : "memory");
}
__device__ __forceinline__ void mbar_wait(unsigned a, unsigned parity) {
    asm volatile(
        "{\n\t.reg .pred P;\n"
        "W%=:\n\t"
        "mbarrier.try_wait.parity.shared.b64 P, [%0], %1;\n\t"
        "@P bra D%=;\n\t"
        "bra W%=;\n"
        "D%=:\n\t}"
        :: "r"(a), "r"(parity) : "memory");
}

__device__ __forceinline__ void issue_load(Smem* sm, const float* __restrict__ x,
                                           int p0, int nk, int iter) {
    if (iter >= TOTAL_ITERS) return;
    const int rel  = (iter < ITERS) ? iter : iter - ITERS;
    const int base = rel * PLB;
    int planes = nk - base; if (planes > PLB) planes = PLB;
    const unsigned bytes = (unsigned)planes * PLANE_BYTES;
    const int slot = iter & (NBUF - 1);
    const unsigned bar = smem_u32(&sm->mbar[slot]);
    const unsigned dst = smem_u32(&sm->buf[slot][0]);
    const float* src = x + ((size_t)(p0 + base)) * HW;
    mbar_expect_tx(bar, bytes);
    bulk_ld(dst, src, bytes, bar);
}

__global__ void __launch_bounds__(NTHREADS, 1) se_fused_kernel(
    const float* __restrict__ x,
    const float* __restrict__ w1, const float* __restrict__ b1,
    const float* __restrict__ w2, const float* __restrict__ b2,
    float* __restrict__ out)
{
    extern __shared__ unsigned char smem_raw[];
    Smem* sm = reinterpret_cast<Smem*>(smem_raw);

    const int tid  = threadIdx.x;
    const int warp = tid >> 5;
    const int lane = tid & 31;
    const int bid  = blockIdx.x;

    const int p0 = (int)(((long long)bid * BC) / GRID);
    const int p1 = (int)(((long long)(bid + 1) * BC) / GRID);
    const int nk = p1 - p0;                    // 53 or 54 planes
    const int b0 = p0 >> 8;
    const int nb = ((p1 - 1) >> 8) - b0 + 1;   // 1 or 2 batch rows

    if (tid == 0) {
        #pragma unroll
        for (int i = 0; i < NBUF; i++) mbar_init(smem_u32(&sm->mbar[i]), 1);
    }
    __syncthreads();
    if (tid == 0) {
        #pragma unroll
        for (int i = 0; i < NBUF; i++) issue_load(sm, x, p0, nk, i);
    }

    float4* __restrict__ o4 = reinterpret_cast<float4*>(out);

    for (int iter = 0; iter < TOTAL_ITERS; ++iter) {
        // ---------- phase boundary: grid barrier + MLP ----------
        if (iter == ITERS) {
            __threadfence();
            __syncthreads();
            if (tid == 0) {
                const unsigned int target = d_gen;
                const unsigned int old = atomicAdd(&d_arrive, 1);
                if (old == GRID - 1) {
                    d_arrive = 0;
                    __threadfence();
                    d_gen = target + 1;
                } else {
                    while (d_gen == target) __nanosleep(64);
                }
                __threadfence();
            }
            __syncthreads();

            for (int idx = tid; idx < nb * C; idx += NTHREADS)
                sm->s[idx >> 8][idx & 255] = d_s[b0 * C + idx];
            __syncthreads();

            for (int j = warp; j < nb * BOT; j += 32) {
                const int bi = j >> 5, o = j & 31;
                const float* __restrict__ w1row = w1 + o * C;
                float acc = 0.0f;
                #pragma unroll
                for (int k = 0; k < 8; k++) {
                    const int c = lane + 32 * k;
                    acc = fmaf(sm->s[bi][c], __ldg(w1row + c), acc);
                }
                #pragma unroll
                for (int off = 16; off > 0; off >>= 1)
                    acc += __shfl_xor_sync(0xffffffffu, acc, off);
                if (lane == 0) sm->h[bi][o] = fmaxf(acc + __ldg(b1 + o), 0.0f);
            }
            __syncthreads();

            if (tid < nk) {
                const int plane = p0 + tid;
                const int c = plane & 255;
                const int bi = (plane >> 8) - b0;
                const float* __restrict__ wrow = w2 + c * BOT;
                float acc = __ldg(b2 + c);
                #pragma unroll
                for (int o = 0; o < BOT; o++)
                    acc = fmaf(sm->h[bi][o], __ldg(wrow + o), acc);
                sm->g[tid] = 1.0f / (1.0f + __expf(-acc));
            }
            __syncthreads();
        }

        const int slot = iter & (NBUF - 1);
        const unsigned parity = (unsigned)((iter >> 2) & 1);
        const int rel = (iter < ITERS) ? iter : iter - ITERS;
        const int base = rel * PLB;
        int planes = nk - base; if (planes > PLB) planes = PLB;
        const int nf4 = planes * HW4;

        mbar_wait(smem_u32(&sm->mbar[slot]), parity);
        const float4* __restrict__ bp =
            reinterpret_cast<const float4*>(sm->buf[slot]);

        if (iter < ITERS) {
            // -------- reduce 2 planes from smem --------
            float accA = 0.f, accB = 0.f;
            {
                int i = tid;
                if (i < nf4) {
                    float4 v = bp[i];
                    float s = (v.x + v.y) + (v.z + v.w);
                    if (i < HW4) accA += s; else accB += s;
                }
                i = tid + NTHREADS;
                if (i < nf4) {                    // i >= 1024 -> always plane 1
                    float4 v = bp[i];
                    accB += (v.x + v.y) + (v.z + v.w);
                }
            }
            #pragma unroll
            for (int o = 16; o > 0; o >>= 1) {
                accA += __shfl_xor_sync(0xffffffffu, accA, o);
                accB += __shfl_xor_sync(0xffffffffu, accB, o);
            }
            if (lane == 0) {
                sm->pb[iter & 1][0][warp] = accA;
                sm->pb[iter & 1][1][warp] = accB;
            }
            __syncthreads();                      // all reads of buf done
            if (tid == 0) issue_load(sm, x, p0, nk, iter + NBUF);
            if (warp < 2) {
                const int plane = base + warp;
                if (plane < nk) {
                    float v = sm->pb[iter & 1][warp][lane];
                    #pragma unroll
                    for (int o = 16; o > 0; o >>= 1)
                        v += __shfl_xor_sync(0xffffffffu, v, o);
                    if (lane == 0)
                        d_s[p0 + plane] = v * (1.0f / (float)HW);
                }
            }
        } else {
            // -------- scale 2 planes from smem -> out --------
            const float g0 = sm->g[base];
            const float g1 = (base + 1 < nk) ? sm->g[base + 1] : 0.f;
            const size_t gbase = (size_t)(p0 + base) * HW4;
            {
                int i = tid;
                if (i < nf4) {
                    float4 v = bp[i];
                    const float gg = (i < HW4) ? g0 : g1;
                    v.x *= gg; v.y *= gg; v.z *= gg; v.w *= gg;
                    __stcs(o4 + gbase + i, v);
                }
                i = tid + NTHREADS;
                if (i < nf4) {
                    float4 v = bp[i];
                    v.x *= g1; v.y *= g1; v.z *= g1; v.w *= g1;
                    __stcs(o4 + gbase + i, v);
                }
            }
            __syncthreads();                      // all reads of buf done
            if (tid == 0) issue_load(sm, x, p0, nk, iter + NBUF);
        }
    }
}

extern "C" void kernel_launch(void* const* d_in, const int* in_sizes, int n_in,
                              void* d_out, int out_size) {
    const float* x  = (const float*)d_in[0];
    const float* w1 = (const float*)d_in[1];
    const float* b1 = (const float*)d_in[2];
    const float* w2 = (const float*)d_in[3];
    const float* b2 = (const float*)d_in[4];
    float* out = (float*)d_out;

    static bool attr_set = false;
    if (!attr_set) {
        cudaFuncSetAttribute(se_fused_kernel,
                             cudaFuncAttributeMaxDynamicSharedMemorySize,
                             (int)sizeof(Smem));
        attr_set = true;
    }
    se_fused_kernel<<<GRID, NTHREADS, sizeof(Smem)>>>(x, w1, b1, w2, b2, out);
}

// round 8
// speedup vs baseline: 1.1695x; 1.1695x over previous
#include <cuda_runtime.h>

// SE block, one persistent kernel, 152 blocks (one per GB300 SM), grid barrier.
// x [32,256,56,56] f32. HW=3136 (=392 float8 / 784 float4). B*C=8192 planes.
//
// Phase 1: half-plane units (196 float8), 256-bit ld.global.nc.L2::evict_last
//          loads (sm_103a requires v8.b32 for evict_last) -> pins x in L2
//          (103MB < 126MB) AND ~1.8x bytes-in-flight per warp.
// Phase 3: REVERSE streaming of the same chunk, __ldcs reads (now L2 hits),
//          __stcs writes (streaming; out must not evict x).

#define C        256
#define BOT      32
#define HW       3136
#define HW4      784
#define HW8      392
#define HP8      196                 // float8 per half-plane unit
#define BC       8192
#define GRID     152
#define NTHREADS 1024

__device__ float d_s[BC];                       // pooled means
__device__ unsigned int d_arrive = 0;
__device__ volatile unsigned int d_gen = 0;

struct __align__(32) F8 { float4 a, b; };

// 256-bit evict_last load, returns the sum of the 8 floats.
__device__ __forceinline__ float ld8_el_sum(const F8* p) {
    unsigned r0, r1, r2, r3, r4, r5, r6, r7;
    asm volatile(
        "ld.global.nc.L2::evict_last.v8.b32 {%0,%1,%2,%3,%4,%5,%6,%7}, [%8];"
        : "=r"(r0), "=r"(r1), "=r"(r2), "=r"(r3),
          "=r"(r4), "=r"(r5), "=r"(r6), "=r"(r7)
        : "l"(p));
    float s0 = __uint_as_float(r0) + __uint_as_float(r1);
    float s1 = __uint_as_float(r2) + __uint_as_float(r3);
    float s2 = __uint_as_float(r4) + __uint_as_float(r5);
    float s3 = __uint_as_float(r6) + __uint_as_float(r7);
    return (s0 + s1) + (s2 + s3);
}

__global__ void __launch_bounds__(NTHREADS, 1) se_fused_kernel(
    const float* __restrict__ x,
    const float* __restrict__ w1, const float* __restrict__ b1,
    const float* __restrict__ w2, const float* __restrict__ b2,
    float* __restrict__ out)
{
    const int tid  = threadIdx.x;
    const int warp = tid >> 5;
    const int lane = tid & 31;
    const int bid  = blockIdx.x;

    const int p0 = (int)(((long long)bid * BC) / GRID);
    const int p1 = (int)(((long long)(bid + 1) * BC) / GRID);
    const int nk = p1 - p0;                  // 53 or 54 planes
    const int nu = nk * 2;                   // half-plane units (106/108)

    __shared__ float sh_part[108];
    __shared__ float sh_s[2][C];
    __shared__ float sh_h[2][BOT];
    __shared__ float sh_g[64];

    // ------------- Phase 1: half-plane sums via 256-bit evict_last loads ------
    const F8* __restrict__ xb8 =
        reinterpret_cast<const F8*>(x + (size_t)p0 * HW);
    for (int u = warp; u < nu; u += 32) {
        const F8* __restrict__ xp = xb8 + (size_t)u * HP8;
        // 196 = 6*32 + 4 : 6 unguarded + 1 predicated 32B load, independent
        float s0 = ld8_el_sum(xp + lane);
        float s1 = ld8_el_sum(xp + lane + 32);
        float s2 = ld8_el_sum(xp + lane + 64);
        float s3 = ld8_el_sum(xp + lane + 96);
        float s4 = ld8_el_sum(xp + lane + 128);
        float s5 = ld8_el_sum(xp + lane + 160);
        float s6 = (lane < 4) ? ld8_el_sum(xp + 192 + lane) : 0.0f;
        float sum = ((s0 + s1) + (s2 + s3)) + ((s4 + s5) + s6);
        #pragma unroll
        for (int o = 16; o > 0; o >>= 1)
            sum += __shfl_xor_sync(0xffffffffu, sum, o);
        if (lane == 0) sh_part[u] = sum;
    }
    __syncthreads();
    if (tid < nk) {
        const float* __restrict__ pp = sh_part + 2 * tid;
        d_s[p0 + tid] = (pp[0] + pp[1]) * (1.0f / (float)HW);
    }

    // ---------------- Grid barrier (replay-safe generation scheme) ------------
    __threadfence();
    __syncthreads();
    if (tid == 0) {
        const unsigned int target = d_gen;
        const unsigned int old = atomicAdd(&d_arrive, 1);
        if (old == GRID - 1) {
            d_arrive = 0;
            __threadfence();
            d_gen = target + 1;              // release
        } else {
            while (d_gen == target) __nanosleep(64);
        }
        __threadfence();
    }
    __syncthreads();

    // ---------------- Phase 2: means -> hidden -> gates for our chunk ---------
    const int b0 = p0 >> 8;
    const int nb = ((p1 - 1) >> 8) - b0 + 1; // 1 or 2 batch rows needed

    for (int idx = tid; idx < nb * C; idx += NTHREADS)
        sh_s[idx >> 8][idx & 255] = d_s[b0 * C + idx];
    __syncthreads();

    for (int j = warp; j < nb * BOT; j += 32) {
        const int bi = j >> 5, o = j & 31;
        const float* __restrict__ w1row = w1 + o * C;
        float acc = 0.0f;
        #pragma unroll
        for (int k = 0; k < 8; k++) {
            const int c = lane + 32 * k;
            acc = fmaf(sh_s[bi][c], __ldg(w1row + c), acc);
        }
        #pragma unroll
        for (int off = 16; off > 0; off >>= 1)
            acc += __shfl_xor_sync(0xffffffffu, acc, off);
        if (lane == 0) sh_h[bi][o] = fmaxf(acc + __ldg(b1 + o), 0.0f);
    }
    __syncthreads();

    if (tid < nk) {
        const int plane = p0 + tid;
        const int c = plane & 255;
        const int bi = (plane >> 8) - b0;
        const float* __restrict__ wrow = w2 + c * BOT;
        float acc = __ldg(b2 + c);
        #pragma unroll
        for (int o = 0; o < BOT; o++)
            acc = fmaf(sh_h[bi][o], __ldg(wrow + o), acc);
        sh_g[tid] = 1.0f / (1.0f + __expf(-acc));
    }
    __syncthreads();

    // ---------------- Phase 3: REVERSE flat streaming over the same chunk -----
    const unsigned int total = (unsigned int)nk * HW4;       // <= 42336
    const int nfull = (int)(total / (8u * NTHREADS));        // full 8-wide iters
    const float4* __restrict__ x4 =
        reinterpret_cast<const float4*>(x) + (size_t)p0 * HW4;
    float4* __restrict__ o4 = reinterpret_cast<float4*>(out) + (size_t)p0 * HW4;

    // tail first (highest addresses = hottest in L1/L2)
    for (unsigned int i = (unsigned int)nfull * 8u * NTHREADS + tid; i < total;
         i += NTHREADS) {
        const float g = sh_g[i / HW4];
        float4 v = __ldcs(x4 + i);
        v.x *= g; v.y *= g; v.z *= g; v.w *= g;
        __stcs(o4 + i, v);
    }
    for (int it = nfull - 1; it >= 0; --it) {
        const unsigned int i = (unsigned int)it * 8u * NTHREADS + tid;
        float4 v0 = __ldcs(x4 + i);
        float4 v1 = __ldcs(x4 + i + 1 * NTHREADS);
        float4 v2 = __ldcs(x4 + i + 2 * NTHREADS);
        float4 v3 = __ldcs(x4 + i + 3 * NTHREADS);
        float4 v4 = __ldcs(x4 + i + 4 * NTHREADS);
        float4 v5 = __ldcs(x4 + i + 5 * NTHREADS);
        float4 v6 = __ldcs(x4 + i + 6 * NTHREADS);
        float4 v7 = __ldcs(x4 + i + 7 * NTHREADS);
        const float g0 = sh_g[(i) / HW4];
        const float g1 = sh_g[(i + 1 * NTHREADS) / HW4];
        const float g2 = sh_g[(i + 2 * NTHREADS) / HW4];
        const float g3 = sh_g[(i + 3 * NTHREADS) / HW4];
        const float g4 = sh_g[(i + 4 * NTHREADS) / HW4];
        const float g5 = sh_g[(i + 5 * NTHREADS) / HW4];
        const float g6 = sh_g[(i + 6 * NTHREADS) / HW4];
        const float g7 = sh_g[(i + 7 * NTHREADS) / HW4];
        v0.x *= g0; v0.y *= g0; v0.z *= g0; v0.w *= g0;
        v1.x *= g1; v1.y *= g1; v1.z *= g1; v1.w *= g1;
        v2.x *= g2; v2.y *= g2; v2.z *= g2; v2.w *= g2;
        v3.x *= g3; v3.y *= g3; v3.z *= g3; v3.w *= g3;
        v4.x *= g4; v4.y *= g4; v4.z *= g4; v4.w *= g4;
        v5.x *= g5; v5.y *= g5; v5.z *= g5; v5.w *= g5;
        v6.x *= g6; v6.y *= g6; v6.z *= g6; v6.w *= g6;
        v7.x *= g7; v7.y *= g7; v7.z *= g7; v7.w *= g7;
        __stcs(o4 + i,                v0);
        __stcs(o4 + i + 1 * NTHREADS, v1);
        __stcs(o4 + i + 2 * NTHREADS, v2);
        __stcs(o4 + i + 3 * NTHREADS, v3);
        __stcs(o4 + i + 4 * NTHREADS, v4);
        __stcs(o4 + i + 5 * NTHREADS, v5);
        __stcs(o4 + i + 6 * NTHREADS, v6);
        __stcs(o4 + i + 7 * NTHREADS, v7);
    }
}

extern "C" void kernel_launch(void* const* d_in, const int* in_sizes, int n_in,
                              void* d_out, int out_size) {
    const float* x  = (const float*)d_in[0];
    const float* w1 = (const float*)d_in[1];
    const float* b1 = (const float*)d_in[2];
    const float* w2 = (const float*)d_in[3];
    const float* b2 = (const float*)d_in[4];
    float* out = (float*)d_out;

    se_fused_kernel<<<GRID, NTHREADS>>>(x, w1, b1, w2, b2, out);
}

// round 9
// speedup vs baseline: 1.2151x; 1.0390x over previous
#include <cuda_runtime.h>

// SE block, one persistent kernel, 152 blocks (one per GB300 SM).
// NO global barrier: per-batch arrival counters. Gate for batch b needs only
// batch b's 256 channel means, and each block owns planes of <=2 batches.
// d_cnt[b] accumulates forever; each launch adds exactly 256 per batch, so
// "cnt % 256 == 0" (tested only after this block's own add) is the replay-safe
// release condition.
//
// Phase 1: quarter-plane units (98 float8), 256-bit evict_last loads
//          (pins x in L2; 103MB < 126MB). 6.75 units/warp -> 3.7% imbalance.
// Phase 3: REVERSE streaming of the same chunk, __ldcs reads / __stcs writes.

#define C        256
#define BOT      32
#define HW       3136
#define HW4      784
#define QP8      98                  // float8 per quarter-plane unit
#define BC       8192
#define GRID     152
#define NTHREADS 1024

__device__ float d_s[BC];                 // pooled means
__device__ unsigned int d_cnt[32];        // per-batch arrival counters (never reset)

struct __align__(32) F8 { float4 a, b; };

__device__ __forceinline__ float ld8_el_sum(const F8* p) {
    unsigned r0, r1, r2, r3, r4, r5, r6, r7;
    asm volatile(
        "ld.global.nc.L2::evict_last.v8.b32 {%0,%1,%2,%3,%4,%5,%6,%7}, [%8];"
        : "=r"(r0), "=r"(r1), "=r"(r2), "=r"(r3),
          "=r"(r4), "=r"(r5), "=r"(r6), "=r"(r7)
        : "l"(p));
    float s0 = __uint_as_float(r0) + __uint_as_float(r1);
    float s1 = __uint_as_float(r2) + __uint_as_float(r3);
    float s2 = __uint_as_float(r4) + __uint_as_float(r5);
    float s3 = __uint_as_float(r6) + __uint_as_float(r7);
    return (s0 + s1) + (s2 + s3);
}

__global__ void __launch_bounds__(NTHREADS, 1) se_fused_kernel(
    const float* __restrict__ x,
    const float* __restrict__ w1, const float* __restrict__ b1,
    const float* __restrict__ w2, const float* __restrict__ b2,
    float* __restrict__ out)
{
    const int tid  = threadIdx.x;
    const int warp = tid >> 5;
    const int lane = tid & 31;
    const int bid  = blockIdx.x;

    const int p0 = (int)(((long long)bid * BC) / GRID);
    const int p1 = (int)(((long long)(bid + 1) * BC) / GRID);
    const int nk = p1 - p0;                  // 53 or 54 planes
    const int nu = nk * 4;                   // quarter-plane units (212/216)

    const int b0 = p0 >> 8;
    const int nb = ((p1 - 1) >> 8) - b0 + 1; // 1 or 2 batches touched
    const int n0 = min((b0 + 1) * C, p1) - p0;   // planes in batch b0
    const int n1 = nk - n0;                      // planes in batch b0+1

    __shared__ float sh_part[216];
    __shared__ float sh_s[2][C];
    __shared__ float sh_h[2][BOT];
    __shared__ float sh_g[64];

    // ------------- Phase 1: quarter-plane sums via 256-bit evict_last ---------
    const F8* __restrict__ xb8 =
        reinterpret_cast<const F8*>(x + (size_t)p0 * HW);
    for (int u = warp; u < nu; u += 32) {
        const F8* __restrict__ xp = xb8 + (size_t)u * QP8;
        // 98 = 3*32 + 2 : 3 unguarded + 1 predicated 32B load
        float s0 = ld8_el_sum(xp + lane);
        float s1 = ld8_el_sum(xp + lane + 32);
        float s2 = ld8_el_sum(xp + lane + 64);
        float s3 = (lane < 2) ? ld8_el_sum(xp + 96 + lane) : 0.0f;
        float sum = (s0 + s1) + (s2 + s3);
        #pragma unroll
        for (int o = 16; o > 0; o >>= 1)
            sum += __shfl_xor_sync(0xffffffffu, sum, o);
        if (lane == 0) sh_part[u] = sum;
    }
    __syncthreads();
    if (tid < nk) {
        const float* __restrict__ pp = sh_part + 4 * tid;
        d_s[p0 + tid] = ((pp[0] + pp[1]) + (pp[2] + pp[3])) * (1.0f / (float)HW);
    }
    __threadfence();                          // publish this thread's d_s write
    __syncthreads();

    // ------------- Per-batch arrive + wait (replay-safe, mod-256) -------------
    if (tid == 0) {
        atomicAdd(&d_cnt[b0], (unsigned)n0);
        if (n1 > 0) atomicAdd(&d_cnt[b0 + 1], (unsigned)n1);
        volatile unsigned int* vc = d_cnt;
        while (vc[b0] & 255u) __nanosleep(32);
        if (n1 > 0)
            while (vc[b0 + 1] & 255u) __nanosleep(32);
        __threadfence();
    }
    __syncthreads();

    // ---------------- Phase 2: means -> hidden -> gates for our chunk ---------
    for (int idx = tid; idx < nb * C; idx += NTHREADS)
        sh_s[idx >> 8][idx & 255] = d_s[b0 * C + idx];
    __syncthreads();

    for (int j = warp; j < nb * BOT; j += 32) {
        const int bi = j >> 5, o = j & 31;
        const float* __restrict__ w1row = w1 + o * C;
        float acc = 0.0f;
        #pragma unroll
        for (int k = 0; k < 8; k++) {
            const int c = lane + 32 * k;
            acc = fmaf(sh_s[bi][c], __ldg(w1row + c), acc);
        }
        #pragma unroll
        for (int off = 16; off > 0; off >>= 1)
            acc += __shfl_xor_sync(0xffffffffu, acc, off);
        if (lane == 0) sh_h[bi][o] = fmaxf(acc + __ldg(b1 + o), 0.0f);
    }
    __syncthreads();

    if (tid < nk) {
        const int plane = p0 + tid;
        const int c = plane & 255;
        const int bi = (plane >> 8) - b0;
        const float* __restrict__ wrow = w2 + c * BOT;
        float acc = __ldg(b2 + c);
        #pragma unroll
        for (int o = 0; o < BOT; o++)
            acc = fmaf(sh_h[bi][o], __ldg(wrow + o), acc);
        sh_g[tid] = 1.0f / (1.0f + __expf(-acc));
    }
    __syncthreads();

    // ---------------- Phase 3: REVERSE flat streaming over the same chunk -----
    const unsigned int total = (unsigned int)nk * HW4;       // <= 42336
    const int nfull = (int)(total / (8u * NTHREADS));        // full 8-wide iters
    const float4* __restrict__ x4 =
        reinterpret_cast<const float4*>(x) + (size_t)p0 * HW4;
    float4* __restrict__ o4 = reinterpret_cast<float4*>(out) + (size_t)p0 * HW4;

    // tail first (highest addresses = hottest in L1/L2)
    for (unsigned int i = (unsigned int)nfull * 8u * NTHREADS + tid; i < total;
         i += NTHREADS) {
        const float g = sh_g[i / HW4];
        float4 v = __ldcs(x4 + i);
        v.x *= g; v.y *= g; v.z *= g; v.w *= g;
        __stcs(o4 + i, v);
    }
    for (int it = nfull - 1; it >= 0; --it) {
        const unsigned int i = (unsigned int)it * 8u * NTHREADS + tid;
        float4 v0 = __ldcs(x4 + i);
        float4 v1 = __ldcs(x4 + i + 1 * NTHREADS);
        float4 v2 = __ldcs(x4 + i + 2 * NTHREADS);
        float4 v3 = __ldcs(x4 + i + 3 * NTHREADS);
        float4 v4 = __ldcs(x4 + i + 4 * NTHREADS);
        float4 v5 = __ldcs(x4 + i + 5 * NTHREADS);
        float4 v6 = __ldcs(x4 + i + 6 * NTHREADS);
        float4 v7 = __ldcs(x4 + i + 7 * NTHREADS);
        const float g0 = sh_g[(i) / HW4];
        const float g1 = sh_g[(i + 1 * NTHREADS) / HW4];
        const float g2 = sh_g[(i + 2 * NTHREADS) / HW4];
        const float g3 = sh_g[(i + 3 * NTHREADS) / HW4];
        const float g4 = sh_g[(i + 4 * NTHREADS) / HW4];
        const float g5 = sh_g[(i + 5 * NTHREADS) / HW4];
        const float g6 = sh_g[(i + 6 * NTHREADS) / HW4];
        const float g7 = sh_g[(i + 7 * NTHREADS) / HW4];
        v0.x *= g0; v0.y *= g0; v0.z *= g0; v0.w *= g0;
        v1.x *= g1; v1.y *= g1; v1.z *= g1; v1.w *= g1;
        v2.x *= g2; v2.y *= g2; v2.z *= g2; v2.w *= g2;
        v3.x *= g3; v3.y *= g3; v3.z *= g3; v3.w *= g3;
        v4.x *= g4; v4.y *= g4; v4.z *= g4; v4.w *= g4;
        v5.x *= g5; v5.y *= g5; v5.z *= g5; v5.w *= g5;
        v6.x *= g6; v6.y *= g6; v6.z *= g6; v6.w *= g6;
        v7.x *= g7; v7.y *= g7; v7.z *= g7; v7.w *= g7;
        __stcs(o4 + i,                v0);
        __stcs(o4 + i + 1 * NTHREADS, v1);
        __stcs(o4 + i + 2 * NTHREADS, v2);
        __stcs(o4 + i + 3 * NTHREADS, v3);
        __stcs(o4 + i + 4 * NTHREADS, v4);
        __stcs(o4 + i + 5 * NTHREADS, v5);
        __stcs(o4 + i + 6 * NTHREADS, v6);
        __stcs(o4 + i + 7 * NTHREADS, v7);
    }
}

extern "C" void kernel_launch(void* const* d_in, const int* in_sizes, int n_in,
                              void* d_out, int out_size) {
    const float* x  = (const float*)d_in[0];
    const float* w1 = (const float*)d_in[1];
    const float* b1 = (const float*)d_in[2];
    const float* w2 = (const float*)d_in[3];
    const float* b2 = (const float*)d_in[4];
    float* out = (float*)d_out;

    se_fused_kernel<<<GRID, NTHREADS>>>(x, w1, b1, w2, b2, out);
}